// round 4
// baseline (speedup 1.0000x reference)
#include <cuda_runtime.h>
#include <cuda_bf16.h>

#define POOL 7
#define NCELL 49
#define C 256

__global__ __launch_bounds__(256, 5) void roi_align_kernel(
    const float* __restrict__ boxes,
    const float* __restrict__ meta,
    const float* __restrict__ f2,
    const float* __restrict__ f3,
    const float* __restrict__ f4,
    const float* __restrict__ f5,
    float* __restrict__ out,
    int N)
{
    const int box_id = blockIdx.x;         // 0 .. B*N-1
    const int batch  = box_id / N;
    const int tid    = threadIdx.x;

    // Per-cell descriptors: packed element offsets of the 4 corners + frac weights
    __shared__ int4   s_off[NCELL];
    __shared__ float2 s_frac[NCELL];       // {fx, fy}

    // --- per-box scalars (redundant per thread; cheap) ---
    const float by1 = boxes[box_id * 4 + 0];
    const float bx1 = boxes[box_id * 4 + 1];
    const float by2 = boxes[box_id * 4 + 2];
    const float bx2 = boxes[box_id * 4 + 3];

    const float area = meta[4] * meta[5];
    const float lvl  = log2f(sqrtf((by2 - by1) * (bx2 - bx1)) / (224.0f / sqrtf(area)));
    float lv = 4.0f + rintf(lvl);          // rintf = round-half-even = jnp.round
    lv = fminf(fmaxf(lv, 2.0f), 5.0f);
    const int level = (int)lv;

    int Hs;
    const float* f;
    if (level == 2)      { Hs = 256; f = f2; }
    else if (level == 3) { Hs = 128; f = f3; }
    else if (level == 4) { Hs = 64;  f = f4; }
    else                 { Hs = 32;  f = f5; }
    const int Ws = Hs;
    const float* base = f + (size_t)batch * Hs * Ws * C;

    // --- build the 49 cell descriptors (one thread per cell) ---
    if (tid < NCELL) {
        const int py = tid / POOL;
        const int px = tid - py * POOL;

        const float ys = by1 * (float)(Hs - 1)
                       + (float)py * ((by2 - by1) * (float)(Hs - 1) / (float)(POOL - 1));
        const float xs = bx1 * (float)(Ws - 1)
                       + (float)px * ((bx2 - bx1) * (float)(Ws - 1) / (float)(POOL - 1));

        const float y0f = floorf(ys);
        const float x0f = floorf(xs);
        int y0 = min(max((int)y0f, 0), Hs - 1);
        int x0 = min(max((int)x0f, 0), Ws - 1);
        const int y1 = min(y0 + 1, Hs - 1);
        const int x1 = min(x0 + 1, Ws - 1);

        s_off[tid]  = make_int4((y0 * Ws + x0) * C, (y0 * Ws + x1) * C,
                                (y1 * Ws + x0) * C, (y1 * Ws + x1) * C);
        s_frac[tid] = make_float2(xs - x0f, ys - y0f);
    }
    __syncthreads();

    // --- main loop: 64 lanes x float4 cover C=256; 4 cell-groups ---
    const int ch = (tid & 63) * 4;         // channel offset
    const int g  = tid >> 6;               // cell group 0..3
    const float* bch   = base + ch;
    float*       obase = out + (size_t)box_id * (NCELL * C) + ch;

    // Process 2 cells per iteration with ALL 8 gathers issued before any math,
    // held in distinct locals so ptxas keeps them in flight (regs allowed: ~48).
    #pragma unroll 1
    for (int k = 0; k < 6; k++) {
        const int c0 = g + 8 * k;
        const int c1 = c0 + 4;

        const int4   offA = s_off[c0];
        const int4   offB = s_off[c1];
        const float2 frA  = s_frac[c0];
        const float2 frB  = s_frac[c1];

        // issue all 8 loads up front
        const float4 tlA = *(const float4*)(bch + offA.x);
        const float4 trA = *(const float4*)(bch + offA.y);
        const float4 blA = *(const float4*)(bch + offA.z);
        const float4 brA = *(const float4*)(bch + offA.w);
        const float4 tlB = *(const float4*)(bch + offB.x);
        const float4 trB = *(const float4*)(bch + offB.y);
        const float4 blB = *(const float4*)(bch + offB.z);
        const float4 brB = *(const float4*)(bch + offB.w);

        float4 oA, oB;
        {
            float top, bot;
            top = tlA.x + (trA.x - tlA.x) * frA.x;  bot = blA.x + (brA.x - blA.x) * frA.x;
            oA.x = top + (bot - top) * frA.y;
            top = tlA.y + (trA.y - tlA.y) * frA.x;  bot = blA.y + (brA.y - blA.y) * frA.x;
            oA.y = top + (bot - top) * frA.y;
            top = tlA.z + (trA.z - tlA.z) * frA.x;  bot = blA.z + (brA.z - blA.z) * frA.x;
            oA.z = top + (bot - top) * frA.y;
            top = tlA.w + (trA.w - tlA.w) * frA.x;  bot = blA.w + (brA.w - blA.w) * frA.x;
            oA.w = top + (bot - top) * frA.y;

            top = tlB.x + (trB.x - tlB.x) * frB.x;  bot = blB.x + (brB.x - blB.x) * frB.x;
            oB.x = top + (bot - top) * frB.y;
            top = tlB.y + (trB.y - tlB.y) * frB.x;  bot = blB.y + (brB.y - blB.y) * frB.x;
            oB.y = top + (bot - top) * frB.y;
            top = tlB.z + (trB.z - tlB.z) * frB.x;  bot = blB.z + (brB.z - blB.z) * frB.x;
            oB.z = top + (bot - top) * frB.y;
            top = tlB.w + (trB.w - tlB.w) * frB.x;  bot = blB.w + (brB.w - blB.w) * frB.x;
            oB.w = top + (bot - top) * frB.y;
        }

        __stwt((float4*)(obase + (size_t)c0 * C), oA);  // streaming: keep L2 for reads
        __stwt((float4*)(obase + (size_t)c1 * C), oB);
    }

    // tail: cell 48 handled by group 0
    if (g == 0) {
        const int4   off = s_off[48];
        const float2 fr  = s_frac[48];
        const float4 tl = *(const float4*)(bch + off.x);
        const float4 tr = *(const float4*)(bch + off.y);
        const float4 bl = *(const float4*)(bch + off.z);
        const float4 br = *(const float4*)(bch + off.w);
        float4 o;
        float top, bot;
        top = tl.x + (tr.x - tl.x) * fr.x;  bot = bl.x + (br.x - bl.x) * fr.x;
        o.x = top + (bot - top) * fr.y;
        top = tl.y + (tr.y - tl.y) * fr.x;  bot = bl.y + (br.y - bl.y) * fr.x;
        o.y = top + (bot - top) * fr.y;
        top = tl.z + (tr.z - tl.z) * fr.x;  bot = bl.z + (br.z - bl.z) * fr.x;
        o.z = top + (bot - top) * fr.y;
        top = tl.w + (tr.w - tl.w) * fr.x;  bot = bl.w + (br.w - bl.w) * fr.x;
        o.w = top + (bot - top) * fr.y;
        __stwt((float4*)(obase + (size_t)48 * C), o);
    }
}

extern "C" void kernel_launch(void* const* d_in, const int* in_sizes, int n_in,
                              void* d_out, int out_size) {
    const float* boxes = (const float*)d_in[0];
    const float* meta  = (const float*)d_in[1];
    const float* f2    = (const float*)d_in[2];
    const float* f3    = (const float*)d_in[3];
    const float* f4    = (const float*)d_in[4];
    const float* f5    = (const float*)d_in[5];
    float* out = (float*)d_out;

    const int BN = in_sizes[0] / 4;                    // total boxes = B*N
    const int B  = in_sizes[2] / (256 * 256 * 256);    // feat2 = B*256*256*C
    const int N  = BN / B;

    roi_align_kernel<<<BN, 256>>>(boxes, meta, f2, f3, f4, f5, out, N);
}